// round 5
// baseline (speedup 1.0000x reference)
#include <cuda_runtime.h>
#include <math.h>

#define N_ATOMS 2048
#define HID     32
#define CUTOFF  2.5f
#define CUTOFF2 6.25f
#define NBLK    512          // 8 i-tiles x 64 j-groups
#define JPB     32           // j atoms per block
#define LUT_N   4096

__device__ double   g_energy = 0.0;
__device__ unsigned g_done   = 0;
__device__ unsigned g_arrive = 0;
__device__ float2   g_lut[LUT_N];

__device__ __forceinline__ float tanh_fast(float x) {
    float y;
    asm("tanh.approx.f32 %0, %1;" : "=f"(y) : "f"(x));
    return y;
}
__device__ __forceinline__ float sqrt_fast(float x) {
    float y;
    asm("sqrt.approx.f32 %0, %1;" : "=f"(y) : "f"(x));
    return y;
}

__global__ __launch_bounds__(256, 4) void fused_kernel(
    const float* __restrict__ xyz,
    const float* __restrict__ cell,
    const float* __restrict__ W1,
    const float* __restrict__ b1,
    const float* __restrict__ W2,
    const float* __restrict__ b2,
    float* __restrict__ out)
{
    const int tid = threadIdx.x;
    const int blk = blockIdx.x;

    // ---------------- Phase 1: build LUT (blocks 0..15 do the work) -------
    // Entry g: ( f(x_g), f(x_{g+1}) - f(x_g) ) for single-load lerp.
    {
        const int g = blk * 256 + tid;
        if (g < LUT_N) {
            const float dxs = CUTOFF / (float)LUT_N;
            const float x0 = (float)g * dxs;
            const float x1 = x0 + dxs;
            float f0 = b2[0], f1 = f0;
            #pragma unroll
            for (int k = 0; k < HID; k++) {
                float w1 = W1[k], bb = b1[k], w2 = W2[k];
                f0 = fmaf(tanh_fast(fmaf(x0, w1, bb)), w2, f0);
                f1 = fmaf(tanh_fast(fmaf(x1, w1, bb)), w2, f1);
            }
            g_lut[g] = make_float2(f0, f1 - f0);
        }
    }

    // ---------------- Grid barrier (all NBLK CTAs resident) ---------------
    if (tid == 0) {
        __threadfence();
        atomicAdd(&g_arrive, 1u);
        while (*(volatile unsigned*)&g_arrive < NBLK) { }
        __threadfence();
    }
    __syncthreads();

    // ---------------- Phase 2: pair energies ------------------------------
    __shared__ float4 sj[JPB];
    __shared__ float  swarp[8];

    const int i_tile = (blk & 7) * 256;
    const int j0     = (blk >> 3) * JPB;
    const int i      = i_tile + tid;

    if (tid < JPB) {
        int j = j0 + tid;
        sj[tid] = make_float4(xyz[3*j], xyz[3*j+1], xyz[3*j+2], 0.f);
    }
    __syncthreads();

    const float Lx = cell[0], Ly = cell[1], Lz = cell[2];
    const float iLx = 1.0f / Lx, iLy = 1.0f / Ly, iLz = 1.0f / Lz;
    const float xi = xyz[3*i], yi = xyz[3*i+1], zi = xyz[3*i+2];
    const float lscale = (float)LUT_N / CUTOFF;

    float acc = 0.0f;

    #pragma unroll
    for (int jj = 0; jj < JPB; jj++) {
        float4 p = sj[jj];
        float dx = p.x - xi;
        float dy = p.y - yi;
        float dz = p.z - zi;
        dx = fmaf(-Lx, rintf(dx * iLx), dx);
        dy = fmaf(-Ly, rintf(dy * iLy), dy);
        dz = fmaf(-Lz, rintf(dz * iLz), dz);
        float dsq = fmaf(dx, dx, fmaf(dy, dy, dz * dz));

        bool ok  = (dsq > 0.0f) && (dsq < CUTOFF2);
        float ds = ok ? dsq : 1.0f;
        float dist = sqrt_fast(ds);
        float t  = dist * lscale;           // < 4096
        int   it = (int)t;
        float fr = t - (float)it;
        float2 e = __ldg(&g_lut[it]);
        float v  = fmaf(fr, e.y, e.x);
        acc += ok ? v : 0.0f;
    }

    // warp reduce in float
    #pragma unroll
    for (int off = 16; off > 0; off >>= 1)
        acc += __shfl_down_sync(0xFFFFFFFFu, acc, off);

    const int lane = tid & 31;
    const int warp = tid >> 5;
    if (lane == 0) swarp[warp] = acc;
    __syncthreads();

    if (warp == 0) {
        float v = (lane < 8) ? swarp[lane] : 0.0f;
        #pragma unroll
        for (int off = 4; off > 0; off >>= 1)
            v += __shfl_down_sync(0xFFFFFFFFu, v, off);
        if (lane == 0) {
            atomicAdd(&g_energy, (double)v);    // RED.F64, pipelined
            __threadfence();
            unsigned old = atomicAdd(&g_done, 1u);
            if (old == NBLK - 1) {
                __threadfence();
                double esum = __longlong_as_double(
                    atomicExch((unsigned long long*)&g_energy, 0ULL));
                out[0] = (float)(0.5 * esum);   // ordered pairs double-count
                // reset protocol state for next graph replay
                atomicExch(&g_arrive, 0u);
                __threadfence();
                atomicExch(&g_done, 0u);
            }
        }
    }
}

extern "C" void kernel_launch(void* const* d_in, const int* in_sizes, int n_in,
                              void* d_out, int out_size)
{
    const float* xyz  = (const float*)d_in[0];
    const float* cell = (const float*)d_in[1];
    const float* W1   = (const float*)d_in[2];
    const float* b1   = (const float*)d_in[3];
    const float* W2   = (const float*)d_in[4];
    const float* b2   = (const float*)d_in[5];
    float* out = (float*)d_out;

    fused_kernel<<<NBLK, 256>>>(xyz, cell, W1, b1, W2, b2, out);
}